// round 9
// baseline (speedup 1.0000x reference)
#include <cuda_runtime.h>
#include <cuda_bf16.h>
#include <cstdint>

// ContrastiveLoss: fused bf16-split HMMA GEMM + online softmax.
// loss = -(1/B^2) * sum_j w_j * S_j
//   S_j = sum_k logits[j,k] - B*max_j - B*log(sum_k exp(logits[j,k]-max_j)+eps)
//   logits = u @ A^T, u[j] = A[j]/T + (A[j] @ Cov[label_j]) / (2 T^3)
// R8: class-grouped u kernel (cov loaded once per class), split fused,
//     GEMM restructured: 12 ldmx4/ks for all 3 products + cp.async dbl-buffer.

#define BN 4096
#define DD 128
#define CN 100
#define NSPLIT 4
#define CTILES ((BN / NSPLIT) / 128)   // 8

__device__ __align__(16) __nv_bfloat16 g_uhi[BN * DD];
__device__ __align__(16) __nv_bfloat16 g_ulo[BN * DD];
__device__ __align__(16) __nv_bfloat16 g_ahi[BN * DD];
__device__ __align__(16) __nv_bfloat16 g_alo[BN * DD];
__device__ float  g_pmax[NSPLIT * BN];
__device__ float  g_pse[NSPLIT * BN];
__device__ float  g_psl[NSPLIT * BN];
__device__ int    g_cnt[CN];
__device__ int    g_coff[CN];
__device__ int    g_fill[CN];
__device__ int    g_order[BN];
__device__ int    g_is64;
__device__ double g_acc;

// ---------------------------------------------------------------- helpers
__device__ __forceinline__ uint32_t smem_u32(const void* p) {
    uint32_t a;
    asm("{ .reg .u64 t; cvta.to.shared.u64 t, %1; cvt.u32.u64 %0, t; }"
        : "=r"(a) : "l"(p));
    return a;
}
__device__ __forceinline__ void ldmx4(uint32_t* r, uint32_t addr) {
    asm volatile("ldmatrix.sync.aligned.m8n8.x4.shared.b16 {%0,%1,%2,%3}, [%4];"
                 : "=r"(r[0]), "=r"(r[1]), "=r"(r[2]), "=r"(r[3]) : "r"(addr));
}
__device__ __forceinline__ void mma_bf16(float* c, const uint32_t* a,
                                         uint32_t b0, uint32_t b1) {
    asm volatile(
        "mma.sync.aligned.m16n8k16.row.col.f32.bf16.bf16.f32 "
        "{%0,%1,%2,%3}, {%4,%5,%6,%7}, {%8,%9}, {%0,%1,%2,%3};"
        : "+f"(c[0]), "+f"(c[1]), "+f"(c[2]), "+f"(c[3])
        : "r"(a[0]), "r"(a[1]), "r"(a[2]), "r"(a[3]), "r"(b0), "r"(b1));
}
#define CP16(dst, src) asm volatile( \
    "cp.async.ca.shared.global [%0], [%1], 16;" :: "r"(dst), "l"(src))
#define CP_COMMIT() asm volatile("cp.async.commit_group;" ::: "memory")
#define CP_WAIT0()  asm volatile("cp.async.wait_group 0;" ::: "memory")

__device__ __forceinline__ uint32_t pk2(float a, float b) {
    __nv_bfloat162 t = __floats2bfloat162_rn(a, b);
    return *(uint32_t*)&t;
}

// ---------------------------------------------------------------- label utils
__device__ __forceinline__ int get_label(const void* L, int t) {
    int v;
    if (g_is64) v = (int)((const long long*)L)[t];
    else        v = ((const int*)L)[t];
    return min(max(v, 0), CN - 1);
}

__global__ void k_detect(const int* __restrict__ Lw) {
    int t = threadIdx.x;
    int odd_nonzero = ((t & 1) && Lw[t] != 0) ? 1 : 0;
    unsigned any = __ballot_sync(0xffffffffu, odd_nonzero);
    __shared__ unsigned s[2];
    s[t >> 5] = any;
    __syncthreads();
    if (t == 0) g_is64 = ((s[0] | s[1]) == 0u) ? 1 : 0;
}

__global__ void k_init() {
    int t = threadIdx.x;
    if (t < CN) { g_cnt[t] = 0; g_fill[t] = 0; }
    if (t == 0) g_acc = 0.0;
}

__global__ void k_hist(const void* __restrict__ labels) {
    int t = blockIdx.x * blockDim.x + threadIdx.x;
    if (t < BN) atomicAdd(&g_cnt[get_label(labels, t)], 1);
}

__global__ void k_prefix() {
    if (threadIdx.x == 0) {
        int s = 0;
        for (int c = 0; c < CN; c++) { g_coff[c] = s; s += g_cnt[c]; }
    }
}

__global__ void k_scatter(const void* __restrict__ labels) {
    int t = blockIdx.x * blockDim.x + threadIdx.x;
    if (t < BN) {
        int c = get_label(labels, t);
        int pos = atomicAdd(&g_fill[c], 1);
        g_order[g_coff[c] + pos] = t;
    }
}

// ---------------------------------------------------------------------------
// Class-grouped u computation + A hi/lo split.
// One CTA per class; Cov[c] resident in smem. 256 threads:
// warp w (0..7) owns rows {w, w+8} of the 16-row chunk; lane owns 4 e-columns.
#define U_SMEM (DD * DD * 4 + 16 * DD * 4 + 64)   // cov 64K + As 8K + rows

__global__ __launch_bounds__(256)
void k_u_grouped(const float* __restrict__ A, const float* __restrict__ Cov) {
    extern __shared__ char dsm[];
    float* covS = (float*)dsm;                 // [DD*DD]
    float* As   = covS + DD * DD;              // [16][DD]
    int*   rows = (int*)(As + 16 * DD);        // [16]
    const int tid = threadIdx.x;
    const int c = blockIdx.x;
    const int cnt = g_cnt[c];
    if (cnt == 0) return;
    const int base = g_coff[c];

    // load Cov[c] into smem
    const float4* Cg = (const float4*)(Cov + (size_t)c * DD * DD);
#pragma unroll
    for (int i = tid; i < DD * DD / 4; i += 256)
        ((float4*)covS)[i] = Cg[i];

    const int rg = tid >> 5;        // warp id: rows rg, rg+8
    const int e4 = (tid & 31) * 4;  // e columns e4..e4+3
    const float invT = (float)(1.0 / 0.07);
    const float s2   = (float)(1.0 / (2.0 * 0.07 * 0.07 * 0.07));

    for (int chunk = 0; chunk < cnt; chunk += 16) {
        __syncthreads();   // protect As/rows from previous iteration readers
        if (tid < 16)
            rows[tid] = (chunk + tid < cnt) ? g_order[base + chunk + tid] : -1;
        __syncthreads();

        // load 16 rows of A into smem; also emit A hi/lo split
#pragma unroll
        for (int i = tid; i < 512; i += 256) {
            int r = i >> 5, cq = i & 31;     // row, float4 idx
            int row = rows[r];
            float4 v = make_float4(0.f, 0.f, 0.f, 0.f);
            if (row >= 0) v = ((const float4*)(A + (size_t)row * DD))[cq];
            ((float4*)&As[r * DD])[cq] = v;
            if (row >= 0) {
                __nv_bfloat16 h0 = __float2bfloat16(v.x);
                __nv_bfloat16 h1 = __float2bfloat16(v.y);
                __nv_bfloat16 h2 = __float2bfloat16(v.z);
                __nv_bfloat16 h3 = __float2bfloat16(v.w);
                uint2 hi, lo;
                hi.x = pk2(v.x, v.y); hi.y = pk2(v.z, v.w);
                lo.x = pk2(v.x - __bfloat162float(h0), v.y - __bfloat162float(h1));
                lo.y = pk2(v.z - __bfloat162float(h2), v.w - __bfloat162float(h3));
                *(uint2*)(g_ahi + (size_t)row * DD + cq * 4) = hi;
                *(uint2*)(g_alo + (size_t)row * DD + cq * 4) = lo;
            }
        }
        __syncthreads();

        float acc[2][4];
#pragma unroll
        for (int r = 0; r < 2; r++)
#pragma unroll
            for (int q = 0; q < 4; q++) acc[r][q] = 0.f;

#pragma unroll 4
        for (int d = 0; d < DD; d++) {
            float4 cv = *(const float4*)(covS + d * DD + e4);
            float a0 = As[rg * DD + d];
            float a1 = As[(rg + 8) * DD + d];
            acc[0][0] = fmaf(a0, cv.x, acc[0][0]);
            acc[0][1] = fmaf(a0, cv.y, acc[0][1]);
            acc[0][2] = fmaf(a0, cv.z, acc[0][2]);
            acc[0][3] = fmaf(a0, cv.w, acc[0][3]);
            acc[1][0] = fmaf(a1, cv.x, acc[1][0]);
            acc[1][1] = fmaf(a1, cv.y, acc[1][1]);
            acc[1][2] = fmaf(a1, cv.z, acc[1][2]);
            acc[1][3] = fmaf(a1, cv.w, acc[1][3]);
        }

        // write u hi/lo for the two rows
#pragma unroll
        for (int r = 0; r < 2; r++) {
            int row = rows[rg + r * 8];
            if (row < 0) continue;
            float uv[4];
#pragma unroll
            for (int q = 0; q < 4; q++)
                uv[q] = As[(rg + r * 8) * DD + e4 + q] * invT + acc[r][q] * s2;
            __nv_bfloat16 h0 = __float2bfloat16(uv[0]);
            __nv_bfloat16 h1 = __float2bfloat16(uv[1]);
            __nv_bfloat16 h2 = __float2bfloat16(uv[2]);
            __nv_bfloat16 h3 = __float2bfloat16(uv[3]);
            uint2 hi, lo;
            hi.x = pk2(uv[0], uv[1]); hi.y = pk2(uv[2], uv[3]);
            lo.x = pk2(uv[0] - __bfloat162float(h0), uv[1] - __bfloat162float(h1));
            lo.y = pk2(uv[2] - __bfloat162float(h2), uv[3] - __bfloat162float(h3));
            *(uint2*)(g_uhi + (size_t)row * DD + e4) = hi;
            *(uint2*)(g_ulo + (size_t)row * DD + e4) = lo;
        }
    }
}

// ---------------------------------------------------------------------------
// Fused HMMA GEMM + online softmax. Grid (BN/128, NSPLIT), 256 threads.
// smem: u hi/lo + double-buffered A hi/lo tiles; row stride 272 B.
#define SROW 272
#define TILE_B (128 * SROW)
#define OFF_UHI 0
#define OFF_ULO (TILE_B)
#define OFF_A   (2 * TILE_B)
#define SMEM_BYTES (6 * TILE_B)

__global__ __launch_bounds__(256, 1)
void k_gemm_mma() {
    extern __shared__ char smem[];
    const uint32_t sb = smem_u32(smem);
    const int tid = threadIdx.x;
    const int wid = tid >> 5;
    const int lid = tid & 31;
    const int warp_m = wid & 3;
    const int warp_n = wid >> 2;
    const int row0 = blockIdx.x * 128;
    const int colbase = blockIdx.y * (BN / NSPLIT);

    const int rsel = (lid & 7) + ((lid >> 3) & 1) * 8;
    const int csel = ((lid >> 4) & 1) * 16;
    uint32_t aoff[2], boff[4];
#pragma unroll
    for (int mf = 0; mf < 2; mf++)
        aoff[mf] = (uint32_t)((warp_m * 32 + mf * 16 + rsel) * SROW + csel);
#pragma unroll
    for (int q = 0; q < 4; q++)
        boff[q] = (uint32_t)((warp_n * 64 + q * 16 + rsel) * SROW + csel);

    // load u tiles (regular stores) + prefetch A tile 0 (cp.async)
#pragma unroll
    for (int i = 0; i < 8; i++) {
        int idx = i * 256 + tid;
        int r = idx >> 4, cq = idx & 15;
        char* dh = smem + OFF_UHI + r * SROW + cq * 16;
        char* dl = smem + OFF_ULO + r * SROW + cq * 16;
        *(uint4*)dh = *((const uint4*)(g_uhi + (size_t)(row0 + r) * DD) + cq);
        *(uint4*)dl = *((const uint4*)(g_ulo + (size_t)(row0 + r) * DD) + cq);
    }
#pragma unroll
    for (int i = 0; i < 8; i++) {
        int idx = i * 256 + tid;
        int r = idx >> 4, cq = idx & 15;
        uint32_t dh = sb + OFF_A + r * SROW + cq * 16;
        CP16(dh, (const char*)(g_ahi + (size_t)(colbase + r) * DD) + cq * 16);
        CP16(dh + TILE_B, (const char*)(g_alo + (size_t)(colbase + r) * DD) + cq * 16);
    }
    CP_COMMIT();
    CP_WAIT0();
    __syncthreads();

    float M[4], L[4], S[4];
#pragma unroll
    for (int i = 0; i < 4; i++) { M[i] = -3.0e38f; L[i] = 0.f; S[i] = 0.f; }

    for (int ct = 0; ct < CTILES; ct++) {
        const uint32_t ab = sb + OFF_A + (uint32_t)(ct & 1) * (2 * TILE_B);

        // prefetch next A tile into the other buffer
        if (ct + 1 < CTILES) {
            const int coln = colbase + (ct + 1) * 128;
            const uint32_t nb = sb + OFF_A + (uint32_t)((ct + 1) & 1) * (2 * TILE_B);
#pragma unroll
            for (int i = 0; i < 8; i++) {
                int idx = i * 256 + tid;
                int r = idx >> 4, cq = idx & 15;
                uint32_t dh = nb + r * SROW + cq * 16;
                CP16(dh, (const char*)(g_ahi + (size_t)(coln + r) * DD) + cq * 16);
                CP16(dh + TILE_B,
                     (const char*)(g_alo + (size_t)(coln + r) * DD) + cq * 16);
            }
        }
        CP_COMMIT();

        float acc[2][8][4];
#pragma unroll
        for (int mf = 0; mf < 2; mf++)
#pragma unroll
            for (int nf = 0; nf < 8; nf++)
#pragma unroll
                for (int c = 0; c < 4; c++) acc[mf][nf][c] = 0.f;

#pragma unroll
        for (int ks = 0; ks < 8; ks++) {
            const uint32_t kb = ks * 32;
            uint32_t uh[2][4], ul[2][4], bh[4][4], bl[4][4];
#pragma unroll
            for (int mf = 0; mf < 2; mf++) {
                ldmx4(uh[mf], sb + OFF_UHI + aoff[mf] + kb);
                ldmx4(ul[mf], sb + OFF_ULO + aoff[mf] + kb);
            }
#pragma unroll
            for (int q = 0; q < 4; q++) {
                ldmx4(bh[q], ab + boff[q] + kb);
                ldmx4(bl[q], ab + TILE_B + boff[q] + kb);
            }
#pragma unroll
            for (int mf = 0; mf < 2; mf++)
#pragma unroll
                for (int q = 0; q < 4; q++) {
                    mma_bf16(acc[mf][2 * q],     uh[mf], bh[q][0], bh[q][2]);
                    mma_bf16(acc[mf][2 * q + 1], uh[mf], bh[q][1], bh[q][3]);
                    mma_bf16(acc[mf][2 * q],     uh[mf], bl[q][0], bl[q][2]);
                    mma_bf16(acc[mf][2 * q + 1], uh[mf], bl[q][1], bl[q][3]);
                    mma_bf16(acc[mf][2 * q],     ul[mf], bh[q][0], bh[q][2]);
                    mma_bf16(acc[mf][2 * q + 1], ul[mf], bh[q][1], bh[q][3]);
                }
        }

        // online softmax update: thread owns 4 rows x 16 cols
#pragma unroll
        for (int ri = 0; ri < 4; ri++) {
            const int mf = ri >> 1, rp = ri & 1;
            float vmax = -3.0e38f;
#pragma unroll
            for (int nf = 0; nf < 8; nf++) {
                vmax = fmaxf(vmax, acc[mf][nf][rp * 2]);
                vmax = fmaxf(vmax, acc[mf][nf][rp * 2 + 1]);
            }
            vmax = fmaxf(vmax, __shfl_xor_sync(0xffffffffu, vmax, 1));
            vmax = fmaxf(vmax, __shfl_xor_sync(0xffffffffu, vmax, 2));
            float nm = fmaxf(M[ri], vmax);
            float se = 0.f, sl = 0.f;
#pragma unroll
            for (int nf = 0; nf < 8; nf++) {
#pragma unroll
                for (int c = 0; c < 2; c++) {
                    float v = acc[mf][nf][rp * 2 + c];
                    se += __expf(v - nm);
                    sl += v;
                }
            }
            se += __shfl_xor_sync(0xffffffffu, se, 1);
            se += __shfl_xor_sync(0xffffffffu, se, 2);
            sl += __shfl_xor_sync(0xffffffffu, sl, 1);
            sl += __shfl_xor_sync(0xffffffffu, sl, 2);
            L[ri] = L[ri] * __expf(M[ri] - nm) + se;
            S[ri] += sl;
            M[ri] = nm;
        }

        CP_WAIT0();
        __syncthreads();
    }

    // merge the two warp_n halves per row (scratch in A-buffer region)
    float* msc = (float*)(smem + OFF_A);   // [2][128]
    float* lsc = msc + 256;
    float* ssc = msc + 512;
    if ((lid & 3) == 0) {
#pragma unroll
        for (int ri = 0; ri < 4; ri++) {
            int row = warp_m * 32 + (ri >> 1) * 16 + (ri & 1) * 8 + (lid >> 2);
            msc[warp_n * 128 + row] = M[ri];
            lsc[warp_n * 128 + row] = L[ri];
            ssc[warp_n * 128 + row] = S[ri];
        }
    }
    __syncthreads();
    if (tid < 128) {
        float m0 = msc[tid], m1 = msc[128 + tid];
        float nm = fmaxf(m0, m1);
        float Lm = lsc[tid] * __expf(m0 - nm) + lsc[128 + tid] * __expf(m1 - nm);
        int o = blockIdx.y * BN + row0 + tid;
        g_pmax[o] = nm;
        g_pse[o]  = Lm;
        g_psl[o]  = ssc[tid] + ssc[128 + tid];
    }
}

// ---------------------------------------------------------------------------
__global__ void k_combine(const void* __restrict__ labels) {
    int j = blockIdx.x * blockDim.x + threadIdx.x;
    float M = -3.0e38f;
#pragma unroll
    for (int s = 0; s < NSPLIT; s++) M = fmaxf(M, g_pmax[s * BN + j]);
    float L = 0.f, Ssum = 0.f;
#pragma unroll
    for (int s = 0; s < NSPLIT; s++) {
        L += g_pse[s * BN + j] * __expf(g_pmax[s * BN + j] - M);
        Ssum += g_psl[s * BN + j];
    }
    float Sj = Ssum - (float)BN * M - (float)BN * logf(L + 1e-12f);
    float mc = (float)g_cnt[get_label(labels, j)];
    float w = mc / (mc + 1e-12f);
    double c = (double)(w * Sj);
#pragma unroll
    for (int o = 16; o >= 1; o >>= 1)
        c += __shfl_xor_sync(0xffffffffu, c, o);
    __shared__ double red[8];
    if ((threadIdx.x & 31) == 0) red[threadIdx.x >> 5] = c;
    __syncthreads();
    if (threadIdx.x < 8) {
        double v = red[threadIdx.x];
#pragma unroll
        for (int o = 4; o >= 1; o >>= 1)
            v += __shfl_xor_sync(0xffu, v, o);
        if (threadIdx.x == 0) atomicAdd(&g_acc, v);
    }
}

__global__ void k_final(float* out) {
    out[0] = (float)(-g_acc / ((double)BN * (double)BN));
}

// ---------------------------------------------------------------------------
extern "C" void kernel_launch(void* const* d_in, const int* in_sizes, int n_in,
                              void* d_out, int out_size) {
    const float* feats = (const float*)d_in[0];
    const void*  labels = d_in[1];
    const float* cov   = (const float*)d_in[2];
    float* out = (float*)d_out;

    cudaFuncSetAttribute(k_gemm_mma,
                         cudaFuncAttributeMaxDynamicSharedMemorySize, SMEM_BYTES);
    cudaFuncSetAttribute(k_u_grouped,
                         cudaFuncAttributeMaxDynamicSharedMemorySize, U_SMEM);

    k_detect<<<1, 64>>>((const int*)labels);
    k_init<<<1, 128>>>();
    k_hist<<<BN / 256, 256>>>(labels);
    k_prefix<<<1, 32>>>();
    k_scatter<<<BN / 256, 256>>>(labels);
    k_u_grouped<<<CN, 256, U_SMEM>>>(feats, cov);
    dim3 grid(BN / 128, NSPLIT);
    k_gemm_mma<<<grid, 256, SMEM_BYTES>>>();
    k_combine<<<BN / 256, 256>>>(labels);
    k_final<<<1, 1>>>(out);
}

// round 11
// speedup vs baseline: 1.0575x; 1.0575x over previous
#include <cuda_runtime.h>
#include <cuda_bf16.h>
#include <cstdint>

// ContrastiveLoss: fused bf16-split HMMA GEMM + online softmax.
// loss = -(1/B^2) * sum_j w_j * S_j
//   S_j = sum_k logits[j,k] - B*max_j - B*log(sum_k exp(logits[j,k]-max_j)+eps)
//   logits = u @ A^T, u[j] = A[j]/T + (A[j] @ Cov[label_j]) / (2 T^3)
// R9: 4-kernel pipeline (pre / u_grouped / gemm / post); parallel scan;
//     per-lane online softmax (no per-tile shuffles).

#define BN 4096
#define DD 128
#define CN 100
#define NSPLIT 4
#define CTILES ((BN / NSPLIT) / 128)   // 8

__device__ __align__(16) __nv_bfloat16 g_uhi[BN * DD];
__device__ __align__(16) __nv_bfloat16 g_ulo[BN * DD];
__device__ __align__(16) __nv_bfloat16 g_ahi[BN * DD];
__device__ __align__(16) __nv_bfloat16 g_alo[BN * DD];
__device__ float  g_pmax[NSPLIT * BN];
__device__ float  g_pse[NSPLIT * BN];
__device__ float  g_psl[NSPLIT * BN];
__device__ int    g_cnt[CN];
__device__ int    g_coff[CN];
__device__ int    g_order[BN];
__device__ int    g_is64;

// ---------------------------------------------------------------- helpers
__device__ __forceinline__ uint32_t smem_u32(const void* p) {
    uint32_t a;
    asm("{ .reg .u64 t; cvta.to.shared.u64 t, %1; cvt.u32.u64 %0, t; }"
        : "=r"(a) : "l"(p));
    return a;
}
__device__ __forceinline__ void ldmx4(uint32_t* r, uint32_t addr) {
    asm volatile("ldmatrix.sync.aligned.m8n8.x4.shared.b16 {%0,%1,%2,%3}, [%4];"
                 : "=r"(r[0]), "=r"(r[1]), "=r"(r[2]), "=r"(r[3]) : "r"(addr));
}
__device__ __forceinline__ void mma_bf16(float* c, const uint32_t* a,
                                         uint32_t b0, uint32_t b1) {
    asm volatile(
        "mma.sync.aligned.m16n8k16.row.col.f32.bf16.bf16.f32 "
        "{%0,%1,%2,%3}, {%4,%5,%6,%7}, {%8,%9}, {%0,%1,%2,%3};"
        : "+f"(c[0]), "+f"(c[1]), "+f"(c[2]), "+f"(c[3])
        : "r"(a[0]), "r"(a[1]), "r"(a[2]), "r"(a[3]), "r"(b0), "r"(b1));
}
#define CP16(dst, src) asm volatile( \
    "cp.async.ca.shared.global [%0], [%1], 16;" :: "r"(dst), "l"(src))
#define CP_COMMIT() asm volatile("cp.async.commit_group;" ::: "memory")
#define CP_WAIT0()  asm volatile("cp.async.wait_group 0;" ::: "memory")

__device__ __forceinline__ uint32_t pk2(float a, float b) {
    __nv_bfloat162 t = __floats2bfloat162_rn(a, b);
    return *(uint32_t*)&t;
}
__device__ __forceinline__ int lab(const void* L, int t, int is64) {
    int v;
    if (is64) v = (int)((const long long*)L)[t];
    else      v = ((const int*)L)[t];
    return min(max(v, 0), CN - 1);
}

// ---------------------------------------------------------------------------
// Preprocessing, single CTA: dtype detect, histogram, scan, scatter.
__global__ __launch_bounds__(1024)
void k_pre(const void* __restrict__ labels) {
    __shared__ int hist[128];
    __shared__ int incl[128];
    __shared__ int fill[128];
    __shared__ int is64_s;
    const int t = threadIdx.x;

    if (t == 0) is64_s = 1;
    if (t < 128) { hist[t] = 0; fill[t] = 0; }
    __syncthreads();
    if (t < 64 && (t & 1) && ((const int*)labels)[t] != 0)
        atomicExch(&is64_s, 0);
    __syncthreads();
    const int is64 = is64_s;
    if (t == 0) g_is64 = is64;

    for (int i = t; i < BN; i += 1024)
        atomicAdd(&hist[lab(labels, i, is64)], 1);
    __syncthreads();

    if (t < 128) incl[t] = hist[t];
    __syncthreads();
#pragma unroll
    for (int off = 1; off < 128; off <<= 1) {
        int v = (t < 128 && t >= off) ? incl[t - off] : 0;
        __syncthreads();
        if (t < 128) incl[t] += v;
        __syncthreads();
    }
    if (t < CN) {
        g_cnt[t] = hist[t];
        g_coff[t] = incl[t] - hist[t];
    }
    __syncthreads();

    for (int i = t; i < BN; i += 1024) {
        int c = lab(labels, i, is64);
        int pos = atomicAdd(&fill[c], 1);
        g_order[(incl[c] - hist[c]) + pos] = i;
    }
}

// ---------------------------------------------------------------------------
// Class-grouped u computation + A hi/lo split. One CTA per class.
#define U_SMEM (DD * DD * 4 + 16 * DD * 4 + 64)

__global__ __launch_bounds__(256)
void k_u_grouped(const float* __restrict__ A, const float* __restrict__ Cov) {
    extern __shared__ char dsm[];
    float* covS = (float*)dsm;
    float* As   = covS + DD * DD;
    int*   rows = (int*)(As + 16 * DD);
    const int tid = threadIdx.x;
    const int c = blockIdx.x;
    const int cnt = g_cnt[c];
    if (cnt == 0) return;
    const int base = g_coff[c];

    const float4* Cg = (const float4*)(Cov + (size_t)c * DD * DD);
#pragma unroll
    for (int i = tid; i < DD * DD / 4; i += 256)
        ((float4*)covS)[i] = Cg[i];

    const int rg = tid >> 5;
    const int e4 = (tid & 31) * 4;
    const float invT = (float)(1.0 / 0.07);
    const float s2   = (float)(1.0 / (2.0 * 0.07 * 0.07 * 0.07));

    for (int chunk = 0; chunk < cnt; chunk += 16) {
        __syncthreads();
        if (tid < 16)
            rows[tid] = (chunk + tid < cnt) ? g_order[base + chunk + tid] : -1;
        __syncthreads();

#pragma unroll
        for (int i = tid; i < 512; i += 256) {
            int r = i >> 5, cq = i & 31;
            int row = rows[r];
            float4 v = make_float4(0.f, 0.f, 0.f, 0.f);
            if (row >= 0) v = ((const float4*)(A + (size_t)row * DD))[cq];
            ((float4*)&As[r * DD])[cq] = v;
            if (row >= 0) {
                __nv_bfloat16 h0 = __float2bfloat16(v.x);
                __nv_bfloat16 h1 = __float2bfloat16(v.y);
                __nv_bfloat16 h2 = __float2bfloat16(v.z);
                __nv_bfloat16 h3 = __float2bfloat16(v.w);
                uint2 hi, lo;
                hi.x = pk2(v.x, v.y); hi.y = pk2(v.z, v.w);
                lo.x = pk2(v.x - __bfloat162float(h0), v.y - __bfloat162float(h1));
                lo.y = pk2(v.z - __bfloat162float(h2), v.w - __bfloat162float(h3));
                *(uint2*)(g_ahi + (size_t)row * DD + cq * 4) = hi;
                *(uint2*)(g_alo + (size_t)row * DD + cq * 4) = lo;
            }
        }
        __syncthreads();

        float acc[2][4];
#pragma unroll
        for (int r = 0; r < 2; r++)
#pragma unroll
            for (int q = 0; q < 4; q++) acc[r][q] = 0.f;

#pragma unroll 4
        for (int d = 0; d < DD; d++) {
            float4 cv = *(const float4*)(covS + d * DD + e4);
            float a0 = As[rg * DD + d];
            float a1 = As[(rg + 8) * DD + d];
            acc[0][0] = fmaf(a0, cv.x, acc[0][0]);
            acc[0][1] = fmaf(a0, cv.y, acc[0][1]);
            acc[0][2] = fmaf(a0, cv.z, acc[0][2]);
            acc[0][3] = fmaf(a0, cv.w, acc[0][3]);
            acc[1][0] = fmaf(a1, cv.x, acc[1][0]);
            acc[1][1] = fmaf(a1, cv.y, acc[1][1]);
            acc[1][2] = fmaf(a1, cv.z, acc[1][2]);
            acc[1][3] = fmaf(a1, cv.w, acc[1][3]);
        }

#pragma unroll
        for (int r = 0; r < 2; r++) {
            int row = rows[rg + r * 8];
            if (row < 0) continue;
            float uv[4];
#pragma unroll
            for (int q = 0; q < 4; q++)
                uv[q] = As[(rg + r * 8) * DD + e4 + q] * invT + acc[r][q] * s2;
            __nv_bfloat16 h0 = __float2bfloat16(uv[0]);
            __nv_bfloat16 h1 = __float2bfloat16(uv[1]);
            __nv_bfloat16 h2 = __float2bfloat16(uv[2]);
            __nv_bfloat16 h3 = __float2bfloat16(uv[3]);
            uint2 hi, lo;
            hi.x = pk2(uv[0], uv[1]); hi.y = pk2(uv[2], uv[3]);
            lo.x = pk2(uv[0] - __bfloat162float(h0), uv[1] - __bfloat162float(h1));
            lo.y = pk2(uv[2] - __bfloat162float(h2), uv[3] - __bfloat162float(h3));
            *(uint2*)(g_uhi + (size_t)row * DD + e4) = hi;
            *(uint2*)(g_ulo + (size_t)row * DD + e4) = lo;
        }
    }
}

// ---------------------------------------------------------------------------
// Fused HMMA GEMM + per-lane online softmax. Grid (BN/128, NSPLIT), 256 thr.
#define SROW 272
#define TILE_B (128 * SROW)
#define OFF_UHI 0
#define OFF_ULO (TILE_B)
#define OFF_A   (2 * TILE_B)
#define SMEM_BYTES (6 * TILE_B)

__global__ __launch_bounds__(256, 1)
void k_gemm_mma() {
    extern __shared__ char smem[];
    const uint32_t sb = smem_u32(smem);
    const int tid = threadIdx.x;
    const int wid = tid >> 5;
    const int lid = tid & 31;
    const int warp_m = wid & 3;
    const int warp_n = wid >> 2;
    const int row0 = blockIdx.x * 128;
    const int colbase = blockIdx.y * (BN / NSPLIT);

    const int rsel = (lid & 7) + ((lid >> 3) & 1) * 8;
    const int csel = ((lid >> 4) & 1) * 16;
    uint32_t aoff[2], boff[4];
#pragma unroll
    for (int mf = 0; mf < 2; mf++)
        aoff[mf] = (uint32_t)((warp_m * 32 + mf * 16 + rsel) * SROW + csel);
#pragma unroll
    for (int q = 0; q < 4; q++)
        boff[q] = (uint32_t)((warp_n * 64 + q * 16 + rsel) * SROW + csel);

#pragma unroll
    for (int i = 0; i < 8; i++) {
        int idx = i * 256 + tid;
        int r = idx >> 4, cq = idx & 15;
        char* dh = smem + OFF_UHI + r * SROW + cq * 16;
        char* dl = smem + OFF_ULO + r * SROW + cq * 16;
        *(uint4*)dh = *((const uint4*)(g_uhi + (size_t)(row0 + r) * DD) + cq);
        *(uint4*)dl = *((const uint4*)(g_ulo + (size_t)(row0 + r) * DD) + cq);
    }
#pragma unroll
    for (int i = 0; i < 8; i++) {
        int idx = i * 256 + tid;
        int r = idx >> 4, cq = idx & 15;
        uint32_t dh = sb + OFF_A + r * SROW + cq * 16;
        CP16(dh, (const char*)(g_ahi + (size_t)(colbase + r) * DD) + cq * 16);
        CP16(dh + TILE_B, (const char*)(g_alo + (size_t)(colbase + r) * DD) + cq * 16);
    }
    CP_COMMIT();
    CP_WAIT0();
    __syncthreads();

    // per-lane online stats (each lane: 4 rows x its private 16 cols)
    float M[4], L[4], S[4];
#pragma unroll
    for (int i = 0; i < 4; i++) { M[i] = -3.0e38f; L[i] = 0.f; S[i] = 0.f; }

    for (int ct = 0; ct < CTILES; ct++) {
        const uint32_t ab = sb + OFF_A + (uint32_t)(ct & 1) * (2 * TILE_B);

        if (ct + 1 < CTILES) {
            const int coln = colbase + (ct + 1) * 128;
            const uint32_t nb = sb + OFF_A + (uint32_t)((ct + 1) & 1) * (2 * TILE_B);
#pragma unroll
            for (int i = 0; i < 8; i++) {
                int idx = i * 256 + tid;
                int r = idx >> 4, cq = idx & 15;
                uint32_t dh = nb + r * SROW + cq * 16;
                CP16(dh, (const char*)(g_ahi + (size_t)(coln + r) * DD) + cq * 16);
                CP16(dh + TILE_B,
                     (const char*)(g_alo + (size_t)(coln + r) * DD) + cq * 16);
            }
        }
        CP_COMMIT();

        float acc[2][8][4];
#pragma unroll
        for (int mf = 0; mf < 2; mf++)
#pragma unroll
            for (int nf = 0; nf < 8; nf++)
#pragma unroll
                for (int c = 0; c < 4; c++) acc[mf][nf][c] = 0.f;

#pragma unroll
        for (int ks = 0; ks < 8; ks++) {
            const uint32_t kb = ks * 32;
            uint32_t uh[2][4], ul[2][4], bh[4][4], bl[4][4];
#pragma unroll
            for (int mf = 0; mf < 2; mf++) {
                ldmx4(uh[mf], sb + OFF_UHI + aoff[mf] + kb);
                ldmx4(ul[mf], sb + OFF_ULO + aoff[mf] + kb);
            }
#pragma unroll
            for (int q = 0; q < 4; q++) {
                ldmx4(bh[q], ab + boff[q] + kb);
                ldmx4(bl[q], ab + TILE_B + boff[q] + kb);
            }
#pragma unroll
            for (int mf = 0; mf < 2; mf++)
#pragma unroll
                for (int q = 0; q < 4; q++) {
                    mma_bf16(acc[mf][2 * q],     uh[mf], bh[q][0], bh[q][2]);
                    mma_bf16(acc[mf][2 * q + 1], uh[mf], bh[q][1], bh[q][3]);
                    mma_bf16(acc[mf][2 * q],     uh[mf], bl[q][0], bl[q][2]);
                    mma_bf16(acc[mf][2 * q + 1], uh[mf], bl[q][1], bl[q][3]);
                    mma_bf16(acc[mf][2 * q],     ul[mf], bh[q][0], bh[q][2]);
                    mma_bf16(acc[mf][2 * q + 1], ul[mf], bh[q][1], bh[q][3]);
                }
        }

        // per-lane online update (no shuffles inside the tile loop)
#pragma unroll
        for (int ri = 0; ri < 4; ri++) {
            const int mf = ri >> 1, rp = ri & 1;
            float vmax = -3.0e38f;
#pragma unroll
            for (int nf = 0; nf < 8; nf++) {
                vmax = fmaxf(vmax, acc[mf][nf][rp * 2]);
                vmax = fmaxf(vmax, acc[mf][nf][rp * 2 + 1]);
            }
            float nm = fmaxf(M[ri], vmax);
            float se = 0.f, sl = 0.f;
#pragma unroll
            for (int nf = 0; nf < 8; nf++) {
#pragma unroll
                for (int c = 0; c < 2; c++) {
                    float v = acc[mf][nf][rp * 2 + c];
                    se += __expf(v - nm);
                    sl += v;
                }
            }
            L[ri] = L[ri] * __expf(M[ri] - nm) + se;
            S[ri] += sl;
            M[ri] = nm;
        }

        CP_WAIT0();
        __syncthreads();
    }

    // merge across the quad (lanes covering the same row)
#pragma unroll
    for (int ri = 0; ri < 4; ri++) {
#pragma unroll
        for (int off = 1; off <= 2; off <<= 1) {
            float om = __shfl_xor_sync(0xffffffffu, M[ri], off);
            float ol = __shfl_xor_sync(0xffffffffu, L[ri], off);
            float os = __shfl_xor_sync(0xffffffffu, S[ri], off);
            float nm = fmaxf(M[ri], om);
            L[ri] = L[ri] * __expf(M[ri] - nm) + ol * __expf(om - nm);
            S[ri] += os;
            M[ri] = nm;
        }
    }

    // merge the two warp_n halves per row
    float* msc = (float*)(smem + OFF_A);   // [2][128]
    float* lsc = msc + 256;
    float* ssc = msc + 512;
    if ((lid & 3) == 0) {
#pragma unroll
        for (int ri = 0; ri < 4; ri++) {
            int row = warp_m * 32 + (ri >> 1) * 16 + (ri & 1) * 8 + (lid >> 2);
            msc[warp_n * 128 + row] = M[ri];
            lsc[warp_n * 128 + row] = L[ri];
            ssc[warp_n * 128 + row] = S[ri];
        }
    }
    __syncthreads();
    if (tid < 128) {
        float m0 = msc[tid], m1 = msc[128 + tid];
        float nm = fmaxf(m0, m1);
        float Lm = lsc[tid] * __expf(m0 - nm) + lsc[128 + tid] * __expf(m1 - nm);
        int o = blockIdx.y * BN + row0 + tid;
        g_pmax[o] = nm;
        g_pse[o]  = Lm;
        g_psl[o]  = ssc[tid] + ssc[128 + tid];
    }
}

// ---------------------------------------------------------------------------
// Combine partials + weighted reduction + final output, single CTA.
__global__ __launch_bounds__(1024)
void k_post(const void* __restrict__ labels, float* __restrict__ out) {
    const int t = threadIdx.x;
    const int is64 = g_is64;
    double acc = 0.0;
    for (int j = t; j < BN; j += 1024) {
        float M = -3.0e38f;
#pragma unroll
        for (int s = 0; s < NSPLIT; s++) M = fmaxf(M, g_pmax[s * BN + j]);
        float L = 0.f, Ssum = 0.f;
#pragma unroll
        for (int s = 0; s < NSPLIT; s++) {
            L += g_pse[s * BN + j] * __expf(g_pmax[s * BN + j] - M);
            Ssum += g_psl[s * BN + j];
        }
        float Sj = Ssum - (float)BN * M - (float)BN * logf(L + 1e-12f);
        float mc = (float)g_cnt[lab(labels, j, is64)];
        float w = mc / (mc + 1e-12f);
        acc += (double)(w * Sj);
    }
#pragma unroll
    for (int o = 16; o >= 1; o >>= 1)
        acc += __shfl_xor_sync(0xffffffffu, acc, o);
    __shared__ double red[32];
    if ((t & 31) == 0) red[t >> 5] = acc;
    __syncthreads();
    if (t < 32) {
        double v = red[t];
#pragma unroll
        for (int o = 16; o >= 1; o >>= 1)
            v += __shfl_xor_sync(0xffffffffu, v, o);
        if (t == 0) out[0] = (float)(-v / ((double)BN * (double)BN));
    }
}

// ---------------------------------------------------------------------------
extern "C" void kernel_launch(void* const* d_in, const int* in_sizes, int n_in,
                              void* d_out, int out_size) {
    const float* feats = (const float*)d_in[0];
    const void*  labels = d_in[1];
    const float* cov   = (const float*)d_in[2];
    float* out = (float*)d_out;

    cudaFuncSetAttribute(k_gemm_mma,
                         cudaFuncAttributeMaxDynamicSharedMemorySize, SMEM_BYTES);
    cudaFuncSetAttribute(k_u_grouped,
                         cudaFuncAttributeMaxDynamicSharedMemorySize, U_SMEM);

    k_pre<<<1, 1024>>>(labels);
    k_u_grouped<<<CN, 256, U_SMEM>>>(feats, cov);
    dim3 grid(BN / 128, NSPLIT);
    k_gemm_mma<<<grid, 256, SMEM_BYTES>>>();
    k_post<<<1, 1024>>>(labels, out);
}

// round 12
// speedup vs baseline: 1.1070x; 1.0468x over previous
#include <cuda_runtime.h>
#include <cuda_bf16.h>
#include <cstdint>

// ContrastiveLoss: fused bf16-split HMMA GEMM + online softmax.
// loss = -(1/B^2) * sum_j w_j * S_j
//   S_j = sum_k logits[j,k] - B*max_j - B*log(sum_k exp(logits[j,k]-max_j)+eps)
//   logits = u @ A^T, u[j] = A[j]/T + (A[j] @ Cov[label_j]) / (2 T^3)
// R11: k_post parallelized to 16 CTAs (was single-CTA, 11.8us) with
//      last-block finalize; __logf. Pipeline stays 4 launches.

#define BN 4096
#define DD 128
#define CN 100
#define NSPLIT 4
#define CTILES ((BN / NSPLIT) / 128)   // 8
#define POST_BLOCKS 16

__device__ __align__(16) __nv_bfloat16 g_uhi[BN * DD];
__device__ __align__(16) __nv_bfloat16 g_ulo[BN * DD];
__device__ __align__(16) __nv_bfloat16 g_ahi[BN * DD];
__device__ __align__(16) __nv_bfloat16 g_alo[BN * DD];
__device__ float  g_pmax[NSPLIT * BN];
__device__ float  g_pse[NSPLIT * BN];
__device__ float  g_psl[NSPLIT * BN];
__device__ int    g_cnt[CN];
__device__ int    g_coff[CN];
__device__ int    g_order[BN];
__device__ int    g_is64;
__device__ double g_acc;
__device__ int    g_ticket;

// ---------------------------------------------------------------- helpers
__device__ __forceinline__ uint32_t smem_u32(const void* p) {
    uint32_t a;
    asm("{ .reg .u64 t; cvta.to.shared.u64 t, %1; cvt.u32.u64 %0, t; }"
        : "=r"(a) : "l"(p));
    return a;
}
__device__ __forceinline__ void ldmx4(uint32_t* r, uint32_t addr) {
    asm volatile("ldmatrix.sync.aligned.m8n8.x4.shared.b16 {%0,%1,%2,%3}, [%4];"
                 : "=r"(r[0]), "=r"(r[1]), "=r"(r[2]), "=r"(r[3]) : "r"(addr));
}
__device__ __forceinline__ void mma_bf16(float* c, const uint32_t* a,
                                         uint32_t b0, uint32_t b1) {
    asm volatile(
        "mma.sync.aligned.m16n8k16.row.col.f32.bf16.bf16.f32 "
        "{%0,%1,%2,%3}, {%4,%5,%6,%7}, {%8,%9}, {%0,%1,%2,%3};"
        : "+f"(c[0]), "+f"(c[1]), "+f"(c[2]), "+f"(c[3])
        : "r"(a[0]), "r"(a[1]), "r"(a[2]), "r"(a[3]), "r"(b0), "r"(b1));
}
#define CP16(dst, src) asm volatile( \
    "cp.async.ca.shared.global [%0], [%1], 16;" :: "r"(dst), "l"(src))
#define CP_COMMIT() asm volatile("cp.async.commit_group;" ::: "memory")
#define CP_WAIT0()  asm volatile("cp.async.wait_group 0;" ::: "memory")

__device__ __forceinline__ uint32_t pk2(float a, float b) {
    __nv_bfloat162 t = __floats2bfloat162_rn(a, b);
    return *(uint32_t*)&t;
}
__device__ __forceinline__ int lab(const void* L, int t, int is64) {
    int v;
    if (is64) v = (int)((const long long*)L)[t];
    else      v = ((const int*)L)[t];
    return min(max(v, 0), CN - 1);
}

// ---------------------------------------------------------------------------
// Preprocessing, single CTA: dtype detect, histogram, scan, scatter, resets.
__global__ __launch_bounds__(1024)
void k_pre(const void* __restrict__ labels) {
    __shared__ int hist[128];
    __shared__ int incl[128];
    __shared__ int fill[128];
    __shared__ int is64_s;
    const int t = threadIdx.x;

    if (t == 0) { is64_s = 1; g_acc = 0.0; g_ticket = 0; }
    if (t < 128) { hist[t] = 0; fill[t] = 0; }
    __syncthreads();
    if (t < 64 && (t & 1) && ((const int*)labels)[t] != 0)
        atomicExch(&is64_s, 0);
    __syncthreads();
    const int is64 = is64_s;
    if (t == 0) g_is64 = is64;

    for (int i = t; i < BN; i += 1024)
        atomicAdd(&hist[lab(labels, i, is64)], 1);
    __syncthreads();

    if (t < 128) incl[t] = hist[t];
    __syncthreads();
#pragma unroll
    for (int off = 1; off < 128; off <<= 1) {
        int v = (t < 128 && t >= off) ? incl[t - off] : 0;
        __syncthreads();
        if (t < 128) incl[t] += v;
        __syncthreads();
    }
    if (t < CN) {
        g_cnt[t] = hist[t];
        g_coff[t] = incl[t] - hist[t];
    }
    __syncthreads();

    for (int i = t; i < BN; i += 1024) {
        int c = lab(labels, i, is64);
        int pos = atomicAdd(&fill[c], 1);
        g_order[(incl[c] - hist[c]) + pos] = i;
    }
}

// ---------------------------------------------------------------------------
// Class-grouped u computation + A hi/lo split. One CTA per class.
#define U_SMEM (DD * DD * 4 + 16 * DD * 4 + 64)

__global__ __launch_bounds__(256)
void k_u_grouped(const float* __restrict__ A, const float* __restrict__ Cov) {
    extern __shared__ char dsm[];
    float* covS = (float*)dsm;
    float* As   = covS + DD * DD;
    int*   rows = (int*)(As + 16 * DD);
    const int tid = threadIdx.x;
    const int c = blockIdx.x;
    const int cnt = g_cnt[c];
    if (cnt == 0) return;
    const int base = g_coff[c];

    const float4* Cg = (const float4*)(Cov + (size_t)c * DD * DD);
#pragma unroll
    for (int i = tid; i < DD * DD / 4; i += 256)
        ((float4*)covS)[i] = Cg[i];

    const int rg = tid >> 5;
    const int e4 = (tid & 31) * 4;
    const float invT = (float)(1.0 / 0.07);
    const float s2   = (float)(1.0 / (2.0 * 0.07 * 0.07 * 0.07));

    for (int chunk = 0; chunk < cnt; chunk += 16) {
        __syncthreads();
        if (tid < 16)
            rows[tid] = (chunk + tid < cnt) ? g_order[base + chunk + tid] : -1;
        __syncthreads();

#pragma unroll
        for (int i = tid; i < 512; i += 256) {
            int r = i >> 5, cq = i & 31;
            int row = rows[r];
            float4 v = make_float4(0.f, 0.f, 0.f, 0.f);
            if (row >= 0) v = ((const float4*)(A + (size_t)row * DD))[cq];
            ((float4*)&As[r * DD])[cq] = v;
            if (row >= 0) {
                __nv_bfloat16 h0 = __float2bfloat16(v.x);
                __nv_bfloat16 h1 = __float2bfloat16(v.y);
                __nv_bfloat16 h2 = __float2bfloat16(v.z);
                __nv_bfloat16 h3 = __float2bfloat16(v.w);
                uint2 hi, lo;
                hi.x = pk2(v.x, v.y); hi.y = pk2(v.z, v.w);
                lo.x = pk2(v.x - __bfloat162float(h0), v.y - __bfloat162float(h1));
                lo.y = pk2(v.z - __bfloat162float(h2), v.w - __bfloat162float(h3));
                *(uint2*)(g_ahi + (size_t)row * DD + cq * 4) = hi;
                *(uint2*)(g_alo + (size_t)row * DD + cq * 4) = lo;
            }
        }
        __syncthreads();

        float acc[2][4];
#pragma unroll
        for (int r = 0; r < 2; r++)
#pragma unroll
            for (int q = 0; q < 4; q++) acc[r][q] = 0.f;

#pragma unroll 4
        for (int d = 0; d < DD; d++) {
            float4 cv = *(const float4*)(covS + d * DD + e4);
            float a0 = As[rg * DD + d];
            float a1 = As[(rg + 8) * DD + d];
            acc[0][0] = fmaf(a0, cv.x, acc[0][0]);
            acc[0][1] = fmaf(a0, cv.y, acc[0][1]);
            acc[0][2] = fmaf(a0, cv.z, acc[0][2]);
            acc[0][3] = fmaf(a0, cv.w, acc[0][3]);
            acc[1][0] = fmaf(a1, cv.x, acc[1][0]);
            acc[1][1] = fmaf(a1, cv.y, acc[1][1]);
            acc[1][2] = fmaf(a1, cv.z, acc[1][2]);
            acc[1][3] = fmaf(a1, cv.w, acc[1][3]);
        }

#pragma unroll
        for (int r = 0; r < 2; r++) {
            int row = rows[rg + r * 8];
            if (row < 0) continue;
            float uv[4];
#pragma unroll
            for (int q = 0; q < 4; q++)
                uv[q] = As[(rg + r * 8) * DD + e4 + q] * invT + acc[r][q] * s2;
            __nv_bfloat16 h0 = __float2bfloat16(uv[0]);
            __nv_bfloat16 h1 = __float2bfloat16(uv[1]);
            __nv_bfloat16 h2 = __float2bfloat16(uv[2]);
            __nv_bfloat16 h3 = __float2bfloat16(uv[3]);
            uint2 hi, lo;
            hi.x = pk2(uv[0], uv[1]); hi.y = pk2(uv[2], uv[3]);
            lo.x = pk2(uv[0] - __bfloat162float(h0), uv[1] - __bfloat162float(h1));
            lo.y = pk2(uv[2] - __bfloat162float(h2), uv[3] - __bfloat162float(h3));
            *(uint2*)(g_uhi + (size_t)row * DD + e4) = hi;
            *(uint2*)(g_ulo + (size_t)row * DD + e4) = lo;
        }
    }
}

// ---------------------------------------------------------------------------
// Fused HMMA GEMM + per-lane online softmax. Grid (BN/128, NSPLIT), 256 thr.
#define SROW 272
#define TILE_B (128 * SROW)
#define OFF_UHI 0
#define OFF_ULO (TILE_B)
#define OFF_A   (2 * TILE_B)
#define SMEM_BYTES (6 * TILE_B)

__global__ __launch_bounds__(256, 1)
void k_gemm_mma() {
    extern __shared__ char smem[];
    const uint32_t sb = smem_u32(smem);
    const int tid = threadIdx.x;
    const int wid = tid >> 5;
    const int lid = tid & 31;
    const int warp_m = wid & 3;
    const int warp_n = wid >> 2;
    const int row0 = blockIdx.x * 128;
    const int colbase = blockIdx.y * (BN / NSPLIT);

    const int rsel = (lid & 7) + ((lid >> 3) & 1) * 8;
    const int csel = ((lid >> 4) & 1) * 16;
    uint32_t aoff[2], boff[4];
#pragma unroll
    for (int mf = 0; mf < 2; mf++)
        aoff[mf] = (uint32_t)((warp_m * 32 + mf * 16 + rsel) * SROW + csel);
#pragma unroll
    for (int q = 0; q < 4; q++)
        boff[q] = (uint32_t)((warp_n * 64 + q * 16 + rsel) * SROW + csel);

#pragma unroll
    for (int i = 0; i < 8; i++) {
        int idx = i * 256 + tid;
        int r = idx >> 4, cq = idx & 15;
        char* dh = smem + OFF_UHI + r * SROW + cq * 16;
        char* dl = smem + OFF_ULO + r * SROW + cq * 16;
        *(uint4*)dh = *((const uint4*)(g_uhi + (size_t)(row0 + r) * DD) + cq);
        *(uint4*)dl = *((const uint4*)(g_ulo + (size_t)(row0 + r) * DD) + cq);
    }
#pragma unroll
    for (int i = 0; i < 8; i++) {
        int idx = i * 256 + tid;
        int r = idx >> 4, cq = idx & 15;
        uint32_t dh = sb + OFF_A + r * SROW + cq * 16;
        CP16(dh, (const char*)(g_ahi + (size_t)(colbase + r) * DD) + cq * 16);
        CP16(dh + TILE_B, (const char*)(g_alo + (size_t)(colbase + r) * DD) + cq * 16);
    }
    CP_COMMIT();
    CP_WAIT0();
    __syncthreads();

    float M[4], L[4], S[4];
#pragma unroll
    for (int i = 0; i < 4; i++) { M[i] = -3.0e38f; L[i] = 0.f; S[i] = 0.f; }

    for (int ct = 0; ct < CTILES; ct++) {
        const uint32_t ab = sb + OFF_A + (uint32_t)(ct & 1) * (2 * TILE_B);

        if (ct + 1 < CTILES) {
            const int coln = colbase + (ct + 1) * 128;
            const uint32_t nb = sb + OFF_A + (uint32_t)((ct + 1) & 1) * (2 * TILE_B);
#pragma unroll
            for (int i = 0; i < 8; i++) {
                int idx = i * 256 + tid;
                int r = idx >> 4, cq = idx & 15;
                uint32_t dh = nb + r * SROW + cq * 16;
                CP16(dh, (const char*)(g_ahi + (size_t)(coln + r) * DD) + cq * 16);
                CP16(dh + TILE_B,
                     (const char*)(g_alo + (size_t)(coln + r) * DD) + cq * 16);
            }
        }
        CP_COMMIT();

        float acc[2][8][4];
#pragma unroll
        for (int mf = 0; mf < 2; mf++)
#pragma unroll
            for (int nf = 0; nf < 8; nf++)
#pragma unroll
                for (int c = 0; c < 4; c++) acc[mf][nf][c] = 0.f;

#pragma unroll
        for (int ks = 0; ks < 8; ks++) {
            const uint32_t kb = ks * 32;
            uint32_t uh[2][4], ul[2][4], bh[4][4], bl[4][4];
#pragma unroll
            for (int mf = 0; mf < 2; mf++) {
                ldmx4(uh[mf], sb + OFF_UHI + aoff[mf] + kb);
                ldmx4(ul[mf], sb + OFF_ULO + aoff[mf] + kb);
            }
#pragma unroll
            for (int q = 0; q < 4; q++) {
                ldmx4(bh[q], ab + boff[q] + kb);
                ldmx4(bl[q], ab + TILE_B + boff[q] + kb);
            }
#pragma unroll
            for (int mf = 0; mf < 2; mf++)
#pragma unroll
                for (int q = 0; q < 4; q++) {
                    mma_bf16(acc[mf][2 * q],     uh[mf], bh[q][0], bh[q][2]);
                    mma_bf16(acc[mf][2 * q + 1], uh[mf], bh[q][1], bh[q][3]);
                    mma_bf16(acc[mf][2 * q],     uh[mf], bl[q][0], bl[q][2]);
                    mma_bf16(acc[mf][2 * q + 1], uh[mf], bl[q][1], bl[q][3]);
                    mma_bf16(acc[mf][2 * q],     ul[mf], bh[q][0], bh[q][2]);
                    mma_bf16(acc[mf][2 * q + 1], ul[mf], bh[q][1], bh[q][3]);
                }
        }

#pragma unroll
        for (int ri = 0; ri < 4; ri++) {
            const int mf = ri >> 1, rp = ri & 1;
            float vmax = -3.0e38f;
#pragma unroll
            for (int nf = 0; nf < 8; nf++) {
                vmax = fmaxf(vmax, acc[mf][nf][rp * 2]);
                vmax = fmaxf(vmax, acc[mf][nf][rp * 2 + 1]);
            }
            float nm = fmaxf(M[ri], vmax);
            float se = 0.f, sl = 0.f;
#pragma unroll
            for (int nf = 0; nf < 8; nf++) {
#pragma unroll
                for (int c = 0; c < 2; c++) {
                    float v = acc[mf][nf][rp * 2 + c];
                    se += __expf(v - nm);
                    sl += v;
                }
            }
            L[ri] = L[ri] * __expf(M[ri] - nm) + se;
            S[ri] += sl;
            M[ri] = nm;
        }

        CP_WAIT0();
        __syncthreads();
    }

#pragma unroll
    for (int ri = 0; ri < 4; ri++) {
#pragma unroll
        for (int off = 1; off <= 2; off <<= 1) {
            float om = __shfl_xor_sync(0xffffffffu, M[ri], off);
            float ol = __shfl_xor_sync(0xffffffffu, L[ri], off);
            float os = __shfl_xor_sync(0xffffffffu, S[ri], off);
            float nm = fmaxf(M[ri], om);
            L[ri] = L[ri] * __expf(M[ri] - nm) + ol * __expf(om - nm);
            S[ri] += os;
            M[ri] = nm;
        }
    }

    float* msc = (float*)(smem + OFF_A);   // [2][128]
    float* lsc = msc + 256;
    float* ssc = msc + 512;
    if ((lid & 3) == 0) {
#pragma unroll
        for (int ri = 0; ri < 4; ri++) {
            int row = warp_m * 32 + (ri >> 1) * 16 + (ri & 1) * 8 + (lid >> 2);
            msc[warp_n * 128 + row] = M[ri];
            lsc[warp_n * 128 + row] = L[ri];
            ssc[warp_n * 128 + row] = S[ri];
        }
    }
    __syncthreads();
    if (tid < 128) {
        float m0 = msc[tid], m1 = msc[128 + tid];
        float nm = fmaxf(m0, m1);
        float Lm = lsc[tid] * __expf(m0 - nm) + lsc[128 + tid] * __expf(m1 - nm);
        int o = blockIdx.y * BN + row0 + tid;
        g_pmax[o] = nm;
        g_pse[o]  = Lm;
        g_psl[o]  = ssc[tid] + ssc[128 + tid];
    }
}

// ---------------------------------------------------------------------------
// Combine + weighted reduction + final output. POST_BLOCKS CTAs x 256 thr,
// one row per thread; last block (ticket) writes the scalar.
__global__ __launch_bounds__(256)
void k_post(const void* __restrict__ labels, float* __restrict__ out) {
    const int t = threadIdx.x;
    const int j = blockIdx.x * 256 + t;
    const int is64 = g_is64;

    float M = -3.0e38f;
#pragma unroll
    for (int s = 0; s < NSPLIT; s++) M = fmaxf(M, g_pmax[s * BN + j]);
    float L = 0.f, Ssum = 0.f;
#pragma unroll
    for (int s = 0; s < NSPLIT; s++) {
        L += g_pse[s * BN + j] * __expf(g_pmax[s * BN + j] - M);
        Ssum += g_psl[s * BN + j];
    }
    float Sj = Ssum - (float)BN * M - (float)BN * __logf(L + 1e-12f);
    float mc = (float)g_cnt[lab(labels, j, is64)];
    float w = mc / (mc + 1e-12f);
    double acc = (double)(w * Sj);

#pragma unroll
    for (int o = 16; o >= 1; o >>= 1)
        acc += __shfl_xor_sync(0xffffffffu, acc, o);
    __shared__ double red[8];
    if ((t & 31) == 0) red[t >> 5] = acc;
    __syncthreads();
    if (t < 8) {
        double v = red[t];
#pragma unroll
        for (int o = 4; o >= 1; o >>= 1)
            v += __shfl_xor_sync(0xffu, v, o);
        if (t == 0) {
            atomicAdd(&g_acc, v);
            __threadfence();
            int done = atomicAdd(&g_ticket, 1);
            if (done == POST_BLOCKS - 1)
                out[0] = (float)(-g_acc / ((double)BN * (double)BN));
        }
    }
}

// ---------------------------------------------------------------------------
extern "C" void kernel_launch(void* const* d_in, const int* in_sizes, int n_in,
                              void* d_out, int out_size) {
    const float* feats = (const float*)d_in[0];
    const void*  labels = d_in[1];
    const float* cov   = (const float*)d_in[2];
    float* out = (float*)d_out;

    cudaFuncSetAttribute(k_gemm_mma,
                         cudaFuncAttributeMaxDynamicSharedMemorySize, SMEM_BYTES);
    cudaFuncSetAttribute(k_u_grouped,
                         cudaFuncAttributeMaxDynamicSharedMemorySize, U_SMEM);

    k_pre<<<1, 1024>>>(labels);
    k_u_grouped<<<CN, 256, U_SMEM>>>(feats, cov);
    dim3 grid(BN / 128, NSPLIT);
    k_gemm_mma<<<grid, 256, SMEM_BYTES>>>();
    k_post<<<POST_BLOCKS, 256>>>(labels, out);
}